// round 1
// baseline (speedup 1.0000x reference)
#include <cuda_runtime.h>
#include <cuda_bf16.h>

// ---------------------------------------------------------------------------
// SR_GNN: hidden=emb[x]; h_in=hid@w_in^T+b_in; h_out=hid@w_out^T+b_out;
// input_in = A[:,:, :N]@h_in + b_iah ; input_out = A[:,:,N:]@h_out + b_oah
// gi = [input_in|input_out]@w_ih^T + b_ih ; gh = hid@w_hh^T + b_hh
// gates -> out.  B=512,N=200,D=128,V=100000.
// ---------------------------------------------------------------------------

#define Bsz 512
#define Nn  200
#define Dd  128
#define Mrows (Bsz*Nn)          // 102400

// scratch (static device globals: no cudaMalloc allowed)
__device__ float g_hidden[(size_t)Mrows * 128];        // 52 MB
__device__ float g_big   [(size_t)Mrows * 640];        // h_in|h_out|gh  262 MB
__device__ float g_inputs[(size_t)Mrows * 256];        // 105 MB
__device__ float g_gi    [(size_t)Mrows * 384];        // 157 MB
__device__ float g_Wt1   [128 * 640];                  // [k][j] of [w_in|w_out|w_hh]
__device__ float g_bias1 [640];
__device__ float g_Wt2   [256 * 384];                  // w_ih^T

// ---- packed f32x2 helpers (sm_103a FFMA2) ----
__device__ __forceinline__ unsigned long long pk2(float lo, float hi) {
    unsigned long long r;
    asm("mov.b64 %0, {%1, %2};" : "=l"(r) : "f"(lo), "f"(hi));
    return r;
}
__device__ __forceinline__ void fma2(unsigned long long& d, unsigned long long a,
                                     unsigned long long b) {
    asm("fma.rn.f32x2 %0, %1, %2, %0;" : "+l"(d) : "l"(a), "l"(b));
}
__device__ __forceinline__ float2 upk2(unsigned long long v) {
    float2 r;
    asm("mov.b64 {%0, %1}, %2;" : "=f"(r.x), "=f"(r.y) : "l"(v));
    return r;
}

// ---- prep: transpose weights into [K][Ncol] layouts + concat biases ----
__global__ void prep_kernel(const float* __restrict__ w_in, const float* __restrict__ b_in,
                            const float* __restrict__ w_out, const float* __restrict__ b_out,
                            const float* __restrict__ w_ih,
                            const float* __restrict__ w_hh, const float* __restrict__ b_hh) {
    int idx = blockIdx.x * blockDim.x + threadIdx.x;
    const int n1 = 128 * 640;          // Wt1
    const int n2 = 256 * 384;          // Wt2
    if (idx < n1) {
        int k = idx / 640, j = idx % 640;
        float v;
        if (j < 128)       v = w_in [j * 128 + k];
        else if (j < 256)  v = w_out[(j - 128) * 128 + k];
        else               v = w_hh [(j - 256) * 128 + k];
        g_Wt1[k * 640 + j] = v;
    } else if (idx < n1 + n2) {
        int t = idx - n1;
        int k = t / 384, j = t % 384;
        g_Wt2[k * 384 + j] = w_ih[j * 256 + k];
    } else if (idx < n1 + n2 + 640) {
        int j = idx - n1 - n2;
        float v;
        if (j < 128)       v = b_in[j];
        else if (j < 256)  v = b_out[j - 128];
        else               v = b_hh[j - 256];
        g_bias1[j] = v;
    }
}

// ---- gather: hidden = emb[x] (float4 wide) ----
__global__ void gather_kernel(const int* __restrict__ x, const float* __restrict__ emb) {
    long long t = (long long)blockIdx.x * blockDim.x + threadIdx.x;
    const long long total4 = (long long)Mrows * 32;   // 128 floats = 32 float4 per row
    if (t >= total4) return;
    int m = (int)(t >> 5);
    int c = (int)(t & 31);
    int v = __ldg(&x[m]);
    ((float4*)g_hidden)[t] = ((const float4*)emb)[(long long)v * 32 + c];
}

// ---- tiled GEMM: C[M,N] = A[M,K] @ B[K,N] + bias[N]; batched via strides ----
#define BM 64
#define BN 64
#define BK 32

__global__ __launch_bounds__(256)
void gemm_bias_kernel(const float* __restrict__ A, const float* __restrict__ B,
                      const float* __restrict__ bias, float* __restrict__ C,
                      int M, int N, int K, int lda, int ldb, int ldc,
                      long long sA, long long sB, long long sC) {
    A += (long long)blockIdx.z * sA;
    B += (long long)blockIdx.z * sB;
    C += (long long)blockIdx.z * sC;

    __shared__ float As[BK][BM + 4];   // [k][m]
    __shared__ float Bs[BK][BN + 4];   // [k][n]

    const int tid = threadIdx.x;
    const int tx = tid & 15;           // n / 4
    const int ty = tid >> 4;           // m / 4
    const int m0 = blockIdx.y * BM;
    const int n0 = blockIdx.x * BN;

    unsigned long long acc[4][2];
    #pragma unroll
    for (int i = 0; i < 4; ++i) { acc[i][0] = 0ull; acc[i][1] = 0ull; }

    const int ntiles = (K + BK - 1) / BK;
    for (int kt = 0; kt < ntiles; ++kt) {
        const int k0 = kt * BK;
        // --- load A tile (64 x 32), transposed into As[k][m] ---
        #pragma unroll
        for (int it = 0; it < 2; ++it) {
            int item = tid + it * 256;         // 0..511
            int row = item >> 3;               // 0..63
            int c4  = item & 7;                // 0..7
            int gm = m0 + row;
            int gk = k0 + c4 * 4;
            float4 v = make_float4(0.f, 0.f, 0.f, 0.f);
            if (gm < M) {
                if (gk + 3 < K) {
                    v = *(const float4*)(A + (long long)gm * lda + gk);
                } else {
                    float* vp = (float*)&v;
                    #pragma unroll
                    for (int q = 0; q < 4; ++q)
                        if (gk + q < K) vp[q] = A[(long long)gm * lda + gk + q];
                }
            }
            As[c4 * 4 + 0][row] = v.x;
            As[c4 * 4 + 1][row] = v.y;
            As[c4 * 4 + 2][row] = v.z;
            As[c4 * 4 + 3][row] = v.w;
        }
        // --- load B tile (32 x 64) ---
        #pragma unroll
        for (int it = 0; it < 2; ++it) {
            int item = tid + it * 256;
            int krow = item >> 4;              // 0..31
            int c4   = item & 15;              // 0..15
            int gk = k0 + krow;
            int gn = n0 + c4 * 4;
            float4 v = make_float4(0.f, 0.f, 0.f, 0.f);
            if (gk < K) {
                if (gn + 3 < N) {
                    v = *(const float4*)(B + (long long)gk * ldb + gn);
                } else {
                    float* vp = (float*)&v;
                    #pragma unroll
                    for (int q = 0; q < 4; ++q)
                        if (gn + q < N) vp[q] = B[(long long)gk * ldb + gn + q];
                }
            }
            *(float4*)&Bs[krow][c4 * 4] = v;
        }
        __syncthreads();

        #pragma unroll
        for (int kk = 0; kk < BK; ++kk) {
            float4 a4 = *(const float4*)&As[kk][ty * 4];
            float4 b4 = *(const float4*)&Bs[kk][tx * 4];
            unsigned long long b01 = pk2(b4.x, b4.y);
            unsigned long long b23 = pk2(b4.z, b4.w);
            float av[4] = {a4.x, a4.y, a4.z, a4.w};
            #pragma unroll
            for (int i = 0; i < 4; ++i) {
                unsigned long long aa = pk2(av[i], av[i]);
                fma2(acc[i][0], aa, b01);
                fma2(acc[i][1], aa, b23);
            }
        }
        __syncthreads();
    }

    // --- epilogue: bias + store ---
    const int gn = n0 + tx * 4;
    float bb[4] = {0.f, 0.f, 0.f, 0.f};
    #pragma unroll
    for (int q = 0; q < 4; ++q)
        if (gn + q < N) bb[q] = bias ? bias[gn + q] : 0.f;

    #pragma unroll
    for (int i = 0; i < 4; ++i) {
        int gm = m0 + ty * 4 + i;
        if (gm >= M) continue;
        float2 v01 = upk2(acc[i][0]);
        float2 v23 = upk2(acc[i][1]);
        float vv[4] = {v01.x, v01.y, v23.x, v23.y};
        float* Crow = C + (long long)gm * ldc;
        #pragma unroll
        for (int q = 0; q < 4; ++q)
            if (gn + q < N) Crow[gn + q] = vv[q] + bb[q];
    }
}

// ---- gates (elementwise epilogue) ----
__global__ void gates_kernel(float* __restrict__ out) {
    long long idx = (long long)blockIdx.x * blockDim.x + threadIdx.x;
    const long long total = (long long)Mrows * 128;
    if (idx >= total) return;
    int row = (int)(idx >> 7);
    int d   = (int)(idx & 127);

    const float* gi = g_gi  + (long long)row * 384;
    const float* gh = g_big + (long long)row * 640 + 256;   // gh cols 256..639
    float i_r = gi[d], i_i = gi[128 + d], i_n = gi[256 + d];
    float h_r = gh[d], h_i = gh[128 + d], h_n = gh[256 + d];
    float hid = g_hidden[(long long)row * 128 + d];

    float gate_input  = 1.f / (1.f + expf(-(i_i + h_i)));
    float gate_reset  = 1.f / (1.f + expf(-(i_r + h_r)));
    float gate_output = tanhf(i_n + gate_reset * h_n);
    out[idx] = gate_output + gate_input * (hid - gate_output);
}

// ---------------------------------------------------------------------------
extern "C" void kernel_launch(void* const* d_in, const int* in_sizes, int n_in,
                              void* d_out, int out_size) {
    const int*   x     = (const int*)  d_in[0];
    const float* A     = (const float*)d_in[1];
    const float* emb   = (const float*)d_in[2];
    const float* w_in  = (const float*)d_in[3];
    const float* b_in  = (const float*)d_in[4];
    const float* w_out = (const float*)d_in[5];
    const float* b_out = (const float*)d_in[6];
    const float* w_ih  = (const float*)d_in[7];
    const float* b_ih  = (const float*)d_in[8];
    const float* w_hh  = (const float*)d_in[9];
    const float* b_hh  = (const float*)d_in[10];
    const float* b_iah = (const float*)d_in[11];
    const float* b_oah = (const float*)d_in[12];
    float* out = (float*)d_out;

    float *p_hidden, *p_big, *p_inputs, *p_gi, *p_Wt1, *p_bias1, *p_Wt2;
    cudaGetSymbolAddress((void**)&p_hidden, g_hidden);
    cudaGetSymbolAddress((void**)&p_big,    g_big);
    cudaGetSymbolAddress((void**)&p_inputs, g_inputs);
    cudaGetSymbolAddress((void**)&p_gi,     g_gi);
    cudaGetSymbolAddress((void**)&p_Wt1,    g_Wt1);
    cudaGetSymbolAddress((void**)&p_bias1,  g_bias1);
    cudaGetSymbolAddress((void**)&p_Wt2,    g_Wt2);

    // 1. prep transposed weights / fused biases
    {
        int total = 128 * 640 + 256 * 384 + 640;
        prep_kernel<<<(total + 255) / 256, 256>>>(w_in, b_in, w_out, b_out, w_ih, w_hh, b_hh);
    }
    // 2. gather hidden = emb[x]
    {
        long long total4 = (long long)Mrows * 32;
        gather_kernel<<<(int)((total4 + 255) / 256), 256>>>(x, emb);
    }
    // 3. big640 = hidden @ Wt1 + bias1   (h_in | h_out | gh)
    {
        dim3 grid(640 / BN, (Mrows + BM - 1) / BM, 1);
        gemm_bias_kernel<<<grid, 256>>>(p_hidden, p_Wt1, p_bias1, p_big,
                                        Mrows, 640, 128, 128, 640, 640, 0, 0, 0);
    }
    // 4a. input_in  = A[:,:, :200] @ h_in + b_iah  -> inputs cols [0:128)
    {
        dim3 grid(128 / BN, (Nn + BM - 1) / BM, Bsz);
        gemm_bias_kernel<<<grid, 256>>>(A, p_big, b_iah, p_inputs,
                                        Nn, 128, Nn, 2 * Nn, 640, 256,
                                        (long long)Nn * 2 * Nn, (long long)Nn * 640,
                                        (long long)Nn * 256);
    }
    // 4b. input_out = A[:,:,200:] @ h_out + b_oah -> inputs cols [128:256)
    {
        dim3 grid(128 / BN, (Nn + BM - 1) / BM, Bsz);
        gemm_bias_kernel<<<grid, 256>>>(A + Nn, p_big + 128, b_oah, p_inputs + 128,
                                        Nn, 128, Nn, 2 * Nn, 640, 256,
                                        (long long)Nn * 2 * Nn, (long long)Nn * 640,
                                        (long long)Nn * 256);
    }
    // 5. gi = inputs @ Wt2 + b_ih
    {
        dim3 grid(384 / BN, (Mrows + BM - 1) / BM, 1);
        gemm_bias_kernel<<<grid, 256>>>(p_inputs, p_Wt2, b_ih, p_gi,
                                        Mrows, 384, 256, 256, 384, 384, 0, 0, 0);
    }
    // 6. gates -> out
    {
        long long total = (long long)Mrows * 128;
        gates_kernel<<<(int)((total + 255) / 256), 256>>>(out);
    }
}

// round 8
// speedup vs baseline: 2.8957x; 2.8957x over previous
#include <cuda_runtime.h>
#include <cuda_bf16.h>
#include <cstdint>

// ---------------------------------------------------------------------------
// SR_GNN via mma.sync tf32 (HMMA path; tcgen05 unavailable: harness compiles
// through compute_103 virtual arch which rejects all sm_103a-only PTX).
//   hidden = emb[x]
//   big    = hidden @ [w_in|w_out|w_hh]^T + [b_in|b_out|b_hh]
//            cols 0..255 stored TRANSPOSED per batch into g_ht; cols 256.. -> g_gh
//   inputs = [ A[:,:, :N]@h_in + b_iah | A[:,:,N:]@h_out + b_oah ]
//   gi     = inputs @ w_ih^T + b_ih
//   out    = gates(gi, gh, hidden)
// B=512, N=200, D=128, V=100000
// ---------------------------------------------------------------------------

#define Bsz 512
#define Nn  200
#define Mrows (Bsz*Nn)                 // 102400
#define HT_HALF (512*128*200)          // floats per half

__device__ float g_hidden[(size_t)Mrows * 128];
__device__ float g_ht    [(size_t)2 * HT_HALF];
__device__ float g_gh    [(size_t)Mrows * 384];
__device__ float g_inputs[(size_t)Mrows * 256];
__device__ float g_gi    [(size_t)Mrows * 384];
__device__ float g_W1    [640 * 128];               // rows: w_in|w_out|w_hh  [N][K]
__device__ float g_bias1 [640];

// ---------------- helpers ----------------
__device__ __forceinline__ uint32_t smem_u32(const void* p) {
    uint32_t a;
    asm("{ .reg .u64 t; cvta.to.shared.u64 t, %1; cvt.u32.u64 %0, t; }" : "=r"(a) : "l"(p));
    return a;
}
__device__ __forceinline__ uint32_t cvt_tf32(float f) {
    uint32_t r;
    asm("cvt.rna.tf32.f32 %0, %1;" : "=r"(r) : "f"(f));
    return r;
}
__device__ __forceinline__ void mma8(float* d, const uint32_t* a, const uint32_t* b) {
    asm volatile("mma.sync.aligned.m16n8k8.row.col.f32.tf32.tf32.f32 "
        "{%0,%1,%2,%3}, {%4,%5,%6,%7}, {%8,%9}, {%0,%1,%2,%3};"
        : "+f"(d[0]), "+f"(d[1]), "+f"(d[2]), "+f"(d[3])
        : "r"(a[0]), "r"(a[1]), "r"(a[2]), "r"(a[3]), "r"(b[0]), "r"(b[1]));
}
#define CP_ASYNC(dst, src, sz) \
    asm volatile("cp.async.cg.shared.global [%0], [%1], 16, %2;" :: "r"(dst), "l"(src), "r"(sz))
#define CP_COMMIT()  asm volatile("cp.async.commit_group;" ::: "memory")
#define CP_WAIT1()   asm volatile("cp.async.wait_group 1;" ::: "memory")
#define CP_WAIT0()   asm volatile("cp.async.wait_group 0;" ::: "memory")

// ---------------- prep / gather ----------------
__global__ void prep_kernel(const float* __restrict__ w_in, const float* __restrict__ b_in,
                            const float* __restrict__ w_out, const float* __restrict__ b_out,
                            const float* __restrict__ w_hh, const float* __restrict__ b_hh) {
    int idx = blockIdx.x * blockDim.x + threadIdx.x;
    if (idx < 640 * 128) {
        int j = idx / 128, k = idx % 128;
        float v;
        if (j < 128)      v = w_in [j * 128 + k];
        else if (j < 256) v = w_out[(j - 128) * 128 + k];
        else              v = w_hh [(j - 256) * 128 + k];
        g_W1[idx] = v;
    } else if (idx < 640 * 128 + 640) {
        int j = idx - 640 * 128;
        g_bias1[j] = (j < 128) ? b_in[j] : (j < 256) ? b_out[j - 128] : b_hh[j - 256];
    }
}

__global__ void gather_kernel(const int* __restrict__ x, const float* __restrict__ emb) {
    long long t = (long long)blockIdx.x * blockDim.x + threadIdx.x;
    const long long total4 = (long long)Mrows * 32;
    if (t >= total4) return;
    int m = (int)(t >> 5), c = (int)(t & 31);
    int v = __ldg(&x[m]);
    ((float4*)g_hidden)[t] = ((const float4*)emb)[(long long)v * 32 + c];
}

// ---------------------------------------------------------------------------
// tf32 mma.sync GEMM: C[M, Ntiles*128] = A[M,K] @ B^T   (B stored [N][K])
// block 128x128, K-chunk 32, double-buffered cp.async, 256 thr (8 warps 2x4),
// warp tile 64x32 -> m16n8k8 grid of 4x4 fragments.
// ep_mode 0: C[gm*ldc + (n - cshift)] = v + bias[n]
// ep_mode 1: n<256 -> transposed per-batch store into ht ; n>=256 -> normal(gh)
// ---------------------------------------------------------------------------
#define LDP 36                       // padded smem row stride (floats)
#define TILE_F (128 * LDP)           // floats per operand tile
#define STAGE_F (2 * TILE_F)         // A + B
#define SMEM_BYTES (2 * STAGE_F * 4) // two stages: 73728 B

__device__ __forceinline__ void load_stage(uint32_t sb, const float* __restrict__ A, int lda,
                                           int a_rows, const float* __restrict__ B, int ldb,
                                           int k0, int K, int tid) {
    #pragma unroll
    for (int it = 0; it < 4; ++it) {
        int item = it * 256 + tid;
        int row = item >> 3, c4 = item & 7;
        int gk = k0 + c4 * 4;
        bool ok = (row < a_rows) && (gk < K);
        const float* src = ok ? (A + (long long)row * lda + gk) : A;
        CP_ASYNC(sb + (uint32_t)(row * LDP + c4 * 4) * 4, src, ok ? 16 : 0);
    }
    #pragma unroll
    for (int it = 0; it < 4; ++it) {
        int item = it * 256 + tid;
        int row = item >> 3, c4 = item & 7;
        int gk = k0 + c4 * 4;
        bool ok = (gk < K);
        const float* src = ok ? (B + (long long)row * ldb + gk) : B;
        CP_ASYNC(sb + (uint32_t)(TILE_F + row * LDP + c4 * 4) * 4, src, ok ? 16 : 0);
    }
}

__global__ __launch_bounds__(256, 2)
void mma_gemm(const float* __restrict__ A, int lda, int Arows, long long sA,
              const float* __restrict__ Bm, int ldb, long long sB,
              const float* __restrict__ bias,
              float* __restrict__ C, int ldc, long long sC, int cshift,
              float* __restrict__ ht,
              int K, int ep_mode) {
    extern __shared__ float smem[];
    const uint32_t sbase = smem_u32(smem);
    const int tid = threadIdx.x;
    const int wid = tid >> 5, lane = tid & 31;
    const int gid = lane >> 2, tig = lane & 3;
    const int wm0 = (wid >> 2) * 64;       // 0 or 64
    const int wn0 = (wid & 3) * 32;        // 0,32,64,96

    A  += (long long)blockIdx.z * sA;
    Bm += (long long)blockIdx.z * sB;
    C  += (long long)blockIdx.z * sC;

    const int n0 = blockIdx.x * 128;
    const int m0 = blockIdx.y * 128;
    const float* Asrc = A + (long long)m0 * lda;
    const float* Bsrc = Bm + (long long)n0 * ldb;
    const int a_rows = (Arows - m0) < 128 ? (Arows - m0) : 128;

    float acc[4][4][4];
    #pragma unroll
    for (int i = 0; i < 4; ++i)
        #pragma unroll
        for (int j = 0; j < 4; ++j)
            #pragma unroll
            for (int q = 0; q < 4; ++q) acc[i][j][q] = 0.f;

    const int nk = (K + 31) / 32;
    load_stage(sbase, Asrc, lda, a_rows, Bsrc, ldb, 0, K, tid);
    CP_COMMIT();

    for (int ck = 0; ck < nk; ++ck) {
        if (ck + 1 < nk) {
            load_stage(sbase + ((ck + 1) & 1) * (uint32_t)STAGE_F * 4,
                       Asrc, lda, a_rows, Bsrc, ldb, (ck + 1) * 32, K, tid);
            CP_COMMIT();
            CP_WAIT1();
        } else {
            CP_WAIT0();
        }
        __syncthreads();

        const float* As_f = smem + (ck & 1) * STAGE_F;
        const float* Bs_f = As_f + TILE_F;
        #pragma unroll
        for (int ks = 0; ks < 4; ++ks) {
            uint32_t af[4][4], bf[4][2];
            #pragma unroll
            for (int tm = 0; tm < 4; ++tm) {
                const float* p = As_f + (wm0 + tm * 16 + gid) * LDP + ks * 8 + tig;
                af[tm][0] = cvt_tf32(p[0]);
                af[tm][1] = cvt_tf32(p[8 * LDP]);
                af[tm][2] = cvt_tf32(p[4]);
                af[tm][3] = cvt_tf32(p[8 * LDP + 4]);
            }
            #pragma unroll
            for (int tn = 0; tn < 4; ++tn) {
                const float* p = Bs_f + (wn0 + tn * 8 + gid) * LDP + ks * 8 + tig;
                bf[tn][0] = cvt_tf32(p[0]);
                bf[tn][1] = cvt_tf32(p[4]);
            }
            #pragma unroll
            for (int tm = 0; tm < 4; ++tm)
                #pragma unroll
                for (int tn = 0; tn < 4; ++tn)
                    mma8(acc[tm][tn], af[tm], bf[tn]);
        }
        __syncthreads();
    }

    // ---- epilogue (direct stores; fragment groups are 32B-contiguous) ----
    #pragma unroll
    for (int tm = 0; tm < 4; ++tm) {
        const int r0 = m0 + wm0 + tm * 16 + gid;
        #pragma unroll
        for (int half_m = 0; half_m < 2; ++half_m) {
            const int gm = r0 + half_m * 8;
            if (gm >= Arows) continue;
            #pragma unroll
            for (int tn = 0; tn < 4; ++tn) {
                const int cb = n0 + wn0 + tn * 8 + tig * 2;
                float v0 = acc[tm][tn][half_m * 2 + 0] + bias[cb];
                float v1 = acc[tm][tn][half_m * 2 + 1] + bias[cb + 1];
                if (ep_mode == 1 && n0 < 256) {
                    int b = gm / 200, i = gm - b * 200;
                    int half = cb >> 7, jj = cb & 127;
                    float* base = ht + (size_t)half * HT_HALF + (size_t)b * 25600;
                    base[jj * 200 + i] = v0;
                    base[(jj + 1) * 200 + i] = v1;
                } else {
                    *(float2*)(C + (size_t)gm * ldc + (cb - cshift)) = make_float2(v0, v1);
                }
            }
        }
    }
}

// ---------------- gates ----------------
__global__ void gates_kernel(float* __restrict__ out) {
    long long idx = (long long)blockIdx.x * blockDim.x + threadIdx.x;
    const long long total = (long long)Mrows * 128;
    if (idx >= total) return;
    int row = (int)(idx >> 7);
    int d   = (int)(idx & 127);

    const float* gi = g_gi + (long long)row * 384;
    const float* gh = g_gh + (long long)row * 384;
    float i_r = gi[d], i_i = gi[128 + d], i_n = gi[256 + d];
    float h_r = gh[d], h_i = gh[128 + d], h_n = gh[256 + d];
    float hid = g_hidden[(long long)row * 128 + d];

    float gate_input  = 1.f / (1.f + expf(-(i_i + h_i)));
    float gate_reset  = 1.f / (1.f + expf(-(i_r + h_r)));
    float gate_output = tanhf(i_n + gate_reset * h_n);
    out[idx] = gate_output + gate_input * (hid - gate_output);
}

// ---------------------------------------------------------------------------
extern "C" void kernel_launch(void* const* d_in, const int* in_sizes, int n_in,
                              void* d_out, int out_size) {
    const int*   x     = (const int*)  d_in[0];
    const float* Amat  = (const float*)d_in[1];
    const float* emb   = (const float*)d_in[2];
    const float* w_in  = (const float*)d_in[3];
    const float* b_in  = (const float*)d_in[4];
    const float* w_out = (const float*)d_in[5];
    const float* b_out = (const float*)d_in[6];
    const float* w_ih  = (const float*)d_in[7];
    const float* b_ih  = (const float*)d_in[8];
    const float* w_hh  = (const float*)d_in[9];
    const float* b_hh  = (const float*)d_in[10];
    const float* b_iah = (const float*)d_in[11];
    const float* b_oah = (const float*)d_in[12];
    float* out = (float*)d_out;

    float *p_hidden, *p_ht, *p_gh, *p_inputs, *p_gi, *p_W1, *p_bias1;
    cudaGetSymbolAddress((void**)&p_hidden, g_hidden);
    cudaGetSymbolAddress((void**)&p_ht,     g_ht);
    cudaGetSymbolAddress((void**)&p_gh,     g_gh);
    cudaGetSymbolAddress((void**)&p_inputs, g_inputs);
    cudaGetSymbolAddress((void**)&p_gi,     g_gi);
    cudaGetSymbolAddress((void**)&p_W1,     g_W1);
    cudaGetSymbolAddress((void**)&p_bias1,  g_bias1);

    cudaFuncSetAttribute(mma_gemm, cudaFuncAttributeMaxDynamicSharedMemorySize, SMEM_BYTES);

    // 1. prep
    prep_kernel<<<(640 * 128 + 640 + 255) / 256, 256>>>(w_in, b_in, w_out, b_out, w_hh, b_hh);
    // 2. gather
    {
        long long total4 = (long long)Mrows * 32;
        gather_kernel<<<(int)((total4 + 255) / 256), 256>>>(x, emb);
    }
    // 3. big = hidden @ W1^T + bias1 ; cols<256 -> ht (transposed), cols>=256 -> gh
    mma_gemm<<<dim3(5, Mrows / 128, 1), 256, SMEM_BYTES>>>(
        p_hidden, 128, Mrows, 0,
        p_W1, 128, 0,
        p_bias1,
        p_gh, 384, 0, 256,
        p_ht,
        128, 1);
    // 4a. input_in = A[:,:, :200] @ h_in + b_iah
    mma_gemm<<<dim3(1, 2, Bsz), 256, SMEM_BYTES>>>(
        Amat, 2 * Nn, Nn, (long long)Nn * 2 * Nn,
        p_ht, Nn, (long long)128 * Nn,
        b_iah,
        p_inputs, 256, (long long)Nn * 256, 0,
        nullptr,
        Nn, 0);
    // 4b. input_out = A[:,:,200:] @ h_out + b_oah
    mma_gemm<<<dim3(1, 2, Bsz), 256, SMEM_BYTES>>>(
        Amat + Nn, 2 * Nn, Nn, (long long)Nn * 2 * Nn,
        p_ht + (size_t)HT_HALF, Nn, (long long)128 * Nn,
        b_oah,
        p_inputs + 128, 256, (long long)Nn * 256, 0,
        nullptr,
        Nn, 0);
    // 5. gi = inputs @ w_ih^T + b_ih
    mma_gemm<<<dim3(3, Mrows / 128, 1), 256, SMEM_BYTES>>>(
        p_inputs, 256, Mrows, 0,
        w_ih, 256, 0,
        b_ih,
        p_gi, 384, 0, 0,
        nullptr,
        256, 0);
    // 6. gates
    {
        long long total = (long long)Mrows * 128;
        gates_kernel<<<(int)((total + 255) / 256), 256>>>(out);
    }
}

// round 10
// speedup vs baseline: 3.0504x; 1.0534x over previous
#include <cuda_runtime.h>
#include <cuda_bf16.h>
#include <cstdint>

// ---------------------------------------------------------------------------
// SR_GNN via mma.sync tf32 (HMMA). All tf32 rounding pre-hoisted out of the
// GEMM inner loops (bit-identical numerics to rounding at fragment load).
//   hidden = emb[x]                       (exact + rounded copies)
//   big    = hidden_r @ [w_in|w_out|w_hh]^T + bias
//            cols<256 -> ht (transposed per batch, ROUNDED); cols>=256 -> gh
//   inputs = [A[:,:, :N]@h_in + b_iah | A[:,:,N:]@h_out + b_oah]  (ROUNDED)
//   gi     = inputs @ w_ih^T + b_ih
//   out    = gates(gi, gh, hidden)
// ---------------------------------------------------------------------------

#define Bsz 512
#define Nn  200
#define Mrows (Bsz*Nn)                 // 102400
#define HT_HALF (512*128*200)

__device__ float g_hidden  [(size_t)Mrows * 128];   // exact (gates)
__device__ float g_hidden_r[(size_t)Mrows * 128];   // tf32-rounded (stage3 A)
__device__ float g_ht    [(size_t)2 * HT_HALF];     // rounded (stage4 B)
__device__ float g_gh    [(size_t)Mrows * 384];
__device__ float g_inputs[(size_t)Mrows * 256];     // rounded (stage5 A)
__device__ float g_gi    [(size_t)Mrows * 384];
__device__ float g_W1    [640 * 128];               // rounded  [N][K]
__device__ float g_W2r   [384 * 256];               // rounded w_ih
__device__ float g_bias1 [640];

// ---------------- helpers ----------------
__device__ __forceinline__ uint32_t smem_u32(const void* p) {
    uint32_t a;
    asm("{ .reg .u64 t; cvta.to.shared.u64 t, %1; cvt.u32.u64 %0, t; }" : "=r"(a) : "l"(p));
    return a;
}
__device__ __forceinline__ uint32_t cvt_tf32(float f) {
    uint32_t r;
    asm("cvt.rna.tf32.f32 %0, %1;" : "=r"(r) : "f"(f));
    return r;
}
__device__ __forceinline__ float round_tf32(float f) { return __uint_as_float(cvt_tf32(f)); }

__device__ __forceinline__ void mma8(float* d, const uint32_t* a, const uint32_t* b) {
    asm volatile("mma.sync.aligned.m16n8k8.row.col.f32.tf32.tf32.f32 "
        "{%0,%1,%2,%3}, {%4,%5,%6,%7}, {%8,%9}, {%0,%1,%2,%3};"
        : "+f"(d[0]), "+f"(d[1]), "+f"(d[2]), "+f"(d[3])
        : "r"(a[0]), "r"(a[1]), "r"(a[2]), "r"(a[3]), "r"(b[0]), "r"(b[1]));
}
#define CP_ASYNC(dst, src, sz) \
    asm volatile("cp.async.cg.shared.global [%0], [%1], 16, %2;" :: "r"(dst), "l"(src), "r"(sz))
#define CP_COMMIT()  asm volatile("cp.async.commit_group;" ::: "memory")
#define CP_WAIT(n)   asm volatile("cp.async.wait_group %0;" :: "n"(n) : "memory")

// ---------------- prep / gather ----------------
__global__ void prep_kernel(const float* __restrict__ w_in, const float* __restrict__ b_in,
                            const float* __restrict__ w_out, const float* __restrict__ b_out,
                            const float* __restrict__ w_ih,
                            const float* __restrict__ w_hh, const float* __restrict__ b_hh) {
    int idx = blockIdx.x * blockDim.x + threadIdx.x;
    if (idx < 640 * 128) {
        int j = idx / 128, k = idx % 128;
        float v;
        if (j < 128)      v = w_in [j * 128 + k];
        else if (j < 256) v = w_out[(j - 128) * 128 + k];
        else              v = w_hh [(j - 256) * 128 + k];
        g_W1[idx] = round_tf32(v);
    } else if (idx < 640 * 128 + 384 * 256) {
        int t = idx - 640 * 128;
        g_W2r[t] = round_tf32(w_ih[t]);
    } else if (idx < 640 * 128 + 384 * 256 + 640) {
        int j = idx - 640 * 128 - 384 * 256;
        g_bias1[j] = (j < 128) ? b_in[j] : (j < 256) ? b_out[j - 128] : b_hh[j - 256];
    }
}

__global__ void gather_kernel(const int* __restrict__ x, const float* __restrict__ emb) {
    long long t = (long long)blockIdx.x * blockDim.x + threadIdx.x;
    const long long total4 = (long long)Mrows * 32;
    if (t >= total4) return;
    int m = (int)(t >> 5), c = (int)(t & 31);
    int v = __ldg(&x[m]);
    float4 e = ((const float4*)emb)[(long long)v * 32 + c];
    ((float4*)g_hidden)[t] = e;
    float4 r;
    r.x = round_tf32(e.x); r.y = round_tf32(e.y);
    r.z = round_tf32(e.z); r.w = round_tf32(e.w);
    ((float4*)g_hidden_r)[t] = r;
}

// ---------------------------------------------------------------------------
// tf32 mma.sync GEMM. block 128x128, K-chunk 32, 3-stage cp.async pipeline,
// 256 thr (8 warps 2x4), warp tile 64x32.
// MODE 1: stage3 (epilogue split: n<256 -> ht transposed rounded; else gh)
// MODE 2: stage4 merged halves (blockIdx.x = half; cvt A frags; rounded store)
// MODE 0: stage5 (plain store)
// ---------------------------------------------------------------------------
#define LDP 36
#define TILE_F (128 * LDP)
#define STAGE_F (2 * TILE_F)
#define SMEM_BYTES (3 * STAGE_F * 4)    // 110592 B

__device__ __forceinline__ void load_stage(uint32_t sb, const float* __restrict__ A, int lda,
                                           int a_rows, const float* __restrict__ B, int ldb,
                                           int k0, int K, int tid) {
    #pragma unroll
    for (int it = 0; it < 4; ++it) {
        int item = it * 256 + tid;
        int row = item >> 3, c4 = item & 7;
        int gk = k0 + c4 * 4;
        bool ok = (row < a_rows) && (gk < K);
        const float* src = ok ? (A + (long long)row * lda + gk) : A;
        CP_ASYNC(sb + (uint32_t)(row * LDP + c4 * 4) * 4, src, ok ? 16 : 0);
    }
    #pragma unroll
    for (int it = 0; it < 4; ++it) {
        int item = it * 256 + tid;
        int row = item >> 3, c4 = item & 7;
        int gk = k0 + c4 * 4;
        bool ok = (gk < K);
        const float* src = ok ? (B + (long long)row * ldb + gk) : B;
        CP_ASYNC(sb + (uint32_t)(TILE_F + row * LDP + c4 * 4) * 4, src, ok ? 16 : 0);
    }
}

template <int MODE>
__global__ __launch_bounds__(256, 2)
void mma_gemm(const float* __restrict__ A, int lda, int Arows, long long sA,
              const float* __restrict__ Bm, int ldb, long long sB,
              const float* __restrict__ bias, const float* __restrict__ bias2,
              float* __restrict__ C, int ldc, long long sC, int cshift,
              float* __restrict__ ht, int K) {
    extern __shared__ float smem[];
    const uint32_t sbase = smem_u32(smem);
    const int tid = threadIdx.x;
    const int wid = tid >> 5, lane = tid & 31;
    const int gid = lane >> 2, tig = lane & 3;
    const int wm0 = (wid >> 2) * 64;
    const int wn0 = (wid & 3) * 32;

    int n0;
    if (MODE == 2) {
        const int half = blockIdx.x;
        A   += (long long)blockIdx.z * sA + half * Nn;
        Bm  += (size_t)half * HT_HALF + (long long)blockIdx.z * sB;
        bias = half ? bias2 : bias;
        C   += (long long)blockIdx.z * sC + half * 128;
        n0 = 0;
    } else {
        A  += (long long)blockIdx.z * sA;
        Bm += (long long)blockIdx.z * sB;
        C  += (long long)blockIdx.z * sC;
        n0 = blockIdx.x * 128;
    }
    const int m0 = blockIdx.y * 128;
    const float* Asrc = A + (long long)m0 * lda;
    const float* Bsrc = Bm + (long long)n0 * ldb;
    const int a_rows = (Arows - m0) < 128 ? (Arows - m0) : 128;

    float acc[4][4][4];
    #pragma unroll
    for (int i = 0; i < 4; ++i)
        #pragma unroll
        for (int j = 0; j < 4; ++j)
            #pragma unroll
            for (int q = 0; q < 4; ++q) acc[i][j][q] = 0.f;

    const int nk = (K + 31) / 32;
    load_stage(sbase, Asrc, lda, a_rows, Bsrc, ldb, 0, K, tid);
    CP_COMMIT();
    if (nk > 1) {
        load_stage(sbase + (uint32_t)STAGE_F * 4, Asrc, lda, a_rows, Bsrc, ldb, 32, K, tid);
        CP_COMMIT();
    }

    int buf = 0;
    for (int ck = 0; ck < nk; ++ck) {
        if (ck + 2 < nk) {
            int nbuf = (buf + 2 >= 3) ? buf - 1 : buf + 2;
            load_stage(sbase + (uint32_t)nbuf * STAGE_F * 4,
                       Asrc, lda, a_rows, Bsrc, ldb, (ck + 2) * 32, K, tid);
            CP_COMMIT();
            CP_WAIT(2);
        } else if (ck + 1 < nk) {
            CP_WAIT(1);
        } else {
            CP_WAIT(0);
        }
        __syncthreads();

        const float* As_f = smem + buf * STAGE_F;
        const float* Bs_f = As_f + TILE_F;
        #pragma unroll
        for (int ks = 0; ks < 4; ++ks) {
            uint32_t af[4][4], bf[4][2];
            #pragma unroll
            for (int tm = 0; tm < 4; ++tm) {
                const float* p = As_f + (wm0 + tm * 16 + gid) * LDP + ks * 8 + tig;
                if (MODE == 2) {
                    af[tm][0] = cvt_tf32(p[0]);
                    af[tm][1] = cvt_tf32(p[8 * LDP]);
                    af[tm][2] = cvt_tf32(p[4]);
                    af[tm][3] = cvt_tf32(p[8 * LDP + 4]);
                } else {
                    af[tm][0] = __float_as_uint(p[0]);
                    af[tm][1] = __float_as_uint(p[8 * LDP]);
                    af[tm][2] = __float_as_uint(p[4]);
                    af[tm][3] = __float_as_uint(p[8 * LDP + 4]);
                }
            }
            #pragma unroll
            for (int tn = 0; tn < 4; ++tn) {
                const float* p = Bs_f + (wn0 + tn * 8 + gid) * LDP + ks * 8 + tig;
                bf[tn][0] = __float_as_uint(p[0]);
                bf[tn][1] = __float_as_uint(p[4]);
            }
            #pragma unroll
            for (int tm = 0; tm < 4; ++tm)
                #pragma unroll
                for (int tn = 0; tn < 4; ++tn)
                    mma8(acc[tm][tn], af[tm], bf[tn]);
        }
        __syncthreads();
        buf = (buf + 1 >= 3) ? 0 : buf + 1;
    }

    // ---- epilogue ----
    #pragma unroll
    for (int tm = 0; tm < 4; ++tm) {
        const int r0 = m0 + wm0 + tm * 16 + gid;
        #pragma unroll
        for (int half_m = 0; half_m < 2; ++half_m) {
            const int gm = r0 + half_m * 8;
            if (gm >= Arows) continue;
            #pragma unroll
            for (int tn = 0; tn < 4; ++tn) {
                const int cb = n0 + wn0 + tn * 8 + tig * 2;
                float v0 = acc[tm][tn][half_m * 2 + 0] + bias[cb];
                float v1 = acc[tm][tn][half_m * 2 + 1] + bias[cb + 1];
                if (MODE == 1 && n0 < 256) {
                    int b = gm / 200, i = gm - b * 200;
                    int half = cb >> 7, jj = cb & 127;
                    float* base = ht + (size_t)half * HT_HALF + (size_t)b * 25600;
                    base[jj * 200 + i]       = round_tf32(v0);
                    base[(jj + 1) * 200 + i] = round_tf32(v1);
                } else if (MODE == 2) {
                    *(float2*)(C + (size_t)gm * ldc + cb) =
                        make_float2(round_tf32(v0), round_tf32(v1));
                } else {
                    *(float2*)(C + (size_t)gm * ldc + (cb - cshift)) = make_float2(v0, v1);
                }
            }
        }
    }
}

// ---------------- gates ----------------
__global__ void gates_kernel(float* __restrict__ out) {
    long long idx = (long long)blockIdx.x * blockDim.x + threadIdx.x;
    const long long total = (long long)Mrows * 128;
    if (idx >= total) return;
    int row = (int)(idx >> 7);
    int d   = (int)(idx & 127);

    const float* gi = g_gi + (long long)row * 384;
    const float* gh = g_gh + (long long)row * 384;
    float i_r = gi[d], i_i = gi[128 + d], i_n = gi[256 + d];
    float h_r = gh[d], h_i = gh[128 + d], h_n = gh[256 + d];
    float hid = g_hidden[(long long)row * 128 + d];

    float gate_input  = 1.f / (1.f + expf(-(i_i + h_i)));
    float gate_reset  = 1.f / (1.f + expf(-(i_r + h_r)));
    float gate_output = tanhf(i_n + gate_reset * h_n);
    out[idx] = gate_output + gate_input * (hid - gate_output);
}

// ---------------------------------------------------------------------------
extern "C" void kernel_launch(void* const* d_in, const int* in_sizes, int n_in,
                              void* d_out, int out_size) {
    const int*   x     = (const int*)  d_in[0];
    const float* Amat  = (const float*)d_in[1];
    const float* emb   = (const float*)d_in[2];
    const float* w_in  = (const float*)d_in[3];
    const float* b_in  = (const float*)d_in[4];
    const float* w_out = (const float*)d_in[5];
    const float* b_out = (const float*)d_in[6];
    const float* w_ih  = (const float*)d_in[7];
    const float* b_ih  = (const float*)d_in[8];
    const float* w_hh  = (const float*)d_in[9];
    const float* b_hh  = (const float*)d_in[10];
    const float* b_iah = (const float*)d_in[11];
    const float* b_oah = (const float*)d_in[12];
    float* out = (float*)d_out;

    float *p_hidden_r, *p_ht, *p_gh, *p_inputs, *p_gi, *p_W1, *p_W2r, *p_bias1;
    cudaGetSymbolAddress((void**)&p_hidden_r, g_hidden_r);
    cudaGetSymbolAddress((void**)&p_ht,     g_ht);
    cudaGetSymbolAddress((void**)&p_gh,     g_gh);
    cudaGetSymbolAddress((void**)&p_inputs, g_inputs);
    cudaGetSymbolAddress((void**)&p_gi,     g_gi);
    cudaGetSymbolAddress((void**)&p_W1,     g_W1);
    cudaGetSymbolAddress((void**)&p_W2r,    g_W2r);
    cudaGetSymbolAddress((void**)&p_bias1,  g_bias1);

    cudaFuncSetAttribute(mma_gemm<0>, cudaFuncAttributeMaxDynamicSharedMemorySize, SMEM_BYTES);
    cudaFuncSetAttribute(mma_gemm<1>, cudaFuncAttributeMaxDynamicSharedMemorySize, SMEM_BYTES);
    cudaFuncSetAttribute(mma_gemm<2>, cudaFuncAttributeMaxDynamicSharedMemorySize, SMEM_BYTES);

    // 1. prep (round weights once)
    {
        int total = 640 * 128 + 384 * 256 + 640;
        prep_kernel<<<(total + 255) / 256, 256>>>(w_in, b_in, w_out, b_out, w_ih, w_hh, b_hh);
    }
    // 2. gather (exact + rounded)
    {
        long long total4 = (long long)Mrows * 32;
        gather_kernel<<<(int)((total4 + 255) / 256), 256>>>(x, emb);
    }
    // 3. big = hidden_r @ W1^T + bias1 ; n<256 -> ht (rounded, transposed), else gh
    mma_gemm<1><<<dim3(5, Mrows / 128, 1), 256, SMEM_BYTES>>>(
        p_hidden_r, 128, Mrows, 0,
        p_W1, 128, 0,
        p_bias1, nullptr,
        p_gh, 384, 0, 256,
        p_ht, 128);
    // 4. inputs = [A_lo@h_in + b_iah | A_hi@h_out + b_oah]   (merged halves)
    mma_gemm<2><<<dim3(2, 2, Bsz), 256, SMEM_BYTES>>>(
        Amat, 2 * Nn, Nn, (long long)Nn * 2 * Nn,
        p_ht, Nn, 25600,
        b_iah, b_oah,
        p_inputs, 256, (long long)Nn * 256, 0,
        nullptr, Nn);
    // 5. gi = inputs @ w_ih^T + b_ih
    mma_gemm<0><<<dim3(3, Mrows / 128, 1), 256, SMEM_BYTES>>>(
        p_inputs, 256, Mrows, 0,
        p_W2r, 256, 0,
        b_ih, nullptr,
        p_gi, 384, 0, 0,
        nullptr, 256);
    // 6. gates
    {
        long long total = (long long)Mrows * 128;
        gates_kernel<<<(int)((total + 255) / 256), 256>>>(out);
    }
}